// round 16
// baseline (speedup 1.0000x reference)
#include <cuda_runtime.h>
#include <cuda_fp16.h>
#include <cstdint>

#define TB      256
#define TILE_H  4
#define TILE_W  64
#define CIN     64
#define COUT    64
#define HH      512
#define WW      512
#define HW      (HH * WW)

// smem layout (bytes)
#define RS_A    528
#define RS_B    144
#define RS_DW   264                           // words; ≡8 mod 32
#define SM_A    0
#define SM_B    (SM_A + CIN * RS_A)          // 33792
#define SM_XBUF (SM_B + CIN * RS_B)          // 43008
// XBUF: 5 buffers x [8 warp-slots][6 rows][18 float4]  (cols bx*64-4 .. bx*64+67)
#define XROW_B  288
#define XCH_B   1728
#define XBUF_B  13824
#define NBUF    5
#define SM_TOTAL (SM_XBUF + NBUF * XBUF_B)   // 112128  (2 CTAs/SM: 224256 <= 227KB)
// D stage overlays A+B+XBUF: 64*264*4 = 67584 <= 112128 OK

#define NCHUNK_W 108                          // 6 rows * 18 chunks per warp-halfpass

__device__ __forceinline__ float axis_a(int i) {
    return (i == 0 || i == HH - 1) ? 0.70710678118654752f : 0.57735026918962576f;
}

__device__ __forceinline__ uint32_t pack_f16(float lo, float hi) {
    uint32_t r;
    asm("cvt.rn.f16x2.f32 %0, %1, %2;" : "=r"(r) : "f"(hi), "f"(lo));
    return r;
}

__device__ __forceinline__ void ldsm_x4t(uint32_t* r, uint32_t addr) {
    asm volatile("ldmatrix.sync.aligned.m8n8.x4.trans.shared.b16 {%0,%1,%2,%3}, [%4];"
                 : "=r"(r[0]), "=r"(r[1]), "=r"(r[2]), "=r"(r[3]) : "r"(addr));
}
__device__ __forceinline__ void mma_f16(float* d, const uint32_t* a, uint32_t b0, uint32_t b1) {
    asm volatile(
        "mma.sync.aligned.m16n8k16.row.col.f32.f16.f16.f32 "
        "{%0,%1,%2,%3}, {%4,%5,%6,%7}, {%8,%9}, {%0,%1,%2,%3};"
        : "+f"(d[0]), "+f"(d[1]), "+f"(d[2]), "+f"(d[3])
        : "r"(a[0]), "r"(a[1]), "r"(a[2]), "r"(a[3]), "r"(b0), "r"(b1));
}

struct StencilCtx {
    float w0, w1, w2, w3;
    int h0;
    uint32_t hbyte;
    bool isH;
};

// stencil + fp16 pack + STS for one half-pass (one channel per warp)
__device__ __forceinline__ void do_halfpass(
    char* smem, uint32_t cons_base, int hp, int wid, int lid, const StencilCtx& cx)
{
    const char* xc = smem + (cons_base - (uint32_t)__cvta_generic_to_shared(smem)) ;
    // cons_base is a shared-space address; recover generic via smem base arithmetic:
    // simpler: caller passes byte offset instead.
    (void)xc;
}

__global__ void __launch_bounds__(TB, 2) gcn_mma_kernel(
    const float* __restrict__ x,     // [B, 64, 512, 512]
    const float* __restrict__ wmat,  // [64, 64] (c, o)
    float* __restrict__ out)         // [B, 64, 512, 512]
{
    extern __shared__ __align__(128) char smem[];
    const uint32_t sb = (uint32_t)__cvta_generic_to_shared(smem);
    float* smemf = (float*)smem;
    const int tid = threadIdx.x;
    const int wid = tid >> 5;
    const int lid = tid & 31;
    const int bx = blockIdx.x, by = blockIdx.y, b = blockIdx.z;

    const int h0 = by * TILE_H;
    const float* xb = x + (size_t)b * CIN * HW;

    // ---- precompute this lane's copy chunks (<=4), once ----
    uint32_t c_dst[4];
    int      c_src[4];
    int      c_ss[4];
    int      c_n = 0;
    #pragma unroll
    for (int k = 0; k < 4; k++) {
        int id = lid + 32 * k;
        if (id < NCHUNK_W) {
            int row = id / 18;
            int j   = id - row * 18;
            int gh  = h0 - 1 + row;
            int g   = bx * TILE_W - 4 + 4 * j;
            bool ok = ((unsigned)gh < HH) && (g >= 0) && (g + 3 < WW);
            c_dst[c_n] = (uint32_t)(row * XROW_B + j * 16);
            c_src[c_n] = ok ? (gh * WW + g) : 0;
            c_ss[c_n]  = ok ? 16 : 0;
            c_n++;
        }
    }
    const uint32_t wslot = sb + SM_XBUF + (uint32_t)(wid * XCH_B);

    // prologue: stream half-passes 0..3 into buffers 0..3 (prefetch depth 4)
    #pragma unroll
    for (int hp = 0; hp < 4; hp++) {
        const float* srcb = xb + (size_t)(hp * 8 + wid) * HW;
        const uint32_t dbase = wslot + (uint32_t)(hp * XBUF_B);
        #pragma unroll
        for (int k = 0; k < 4; k++)
            if (k < c_n)
                asm volatile("cp.async.cg.shared.global [%0], [%1], 16, %2;"
                             :: "r"(dbase + c_dst[k]), "l"(srcb + c_src[k]), "r"(c_ss[k]));
        asm volatile("cp.async.commit_group;");
    }

    // ---- B tile: W[c][o] -> smem [c][o] fp16, coalesced 32-bit STS ----
    {
        const float2* w2 = (const float2*)wmat;
        #pragma unroll
        for (int it = tid; it < CIN * COUT / 2; it += TB) {
            int c  = it >> 5;
            int o2 = it & 31;
            float2 v = w2[it];
            *(uint32_t*)(smem + SM_B + (uint32_t)(c * RS_B + o2 * 4)) = pack_f16(v.x, v.y);
        }
    }

    // per-lane stencil constants (lane owns 2 cols: cbase, cbase+1)
    const int cbase = bx * TILE_W + 2 * lid;
    const bool lok = (cbase - 1 >= 0);
    const bool rok = (cbase + 2 <= WW - 1);
    const float w0 = lok ? axis_a(cbase - 1) : 0.0f;
    const float w1 = axis_a(cbase);
    const float w2 = axis_a(cbase + 1);
    const float w3 = rok ? axis_a(cbase + 2) : 0.0f;

    // MMA fragment addresses
    const uint32_t a_off = (uint32_t)((lid & 7) + ((lid >> 4) & 1) * 8) * RS_A
                         + (uint32_t)(wid * 32 + ((lid >> 3) & 1) * 8) * 2;
    const uint32_t b_off = (uint32_t)((lid & 7) + ((lid >> 3) & 1) * 8) * RS_B
                         + (uint32_t)(((lid >> 4) & 1) * 8) * 2;

    float acc[2][8][4];
    #pragma unroll
    for (int mt = 0; mt < 2; mt++)
        #pragma unroll
        for (int nt = 0; nt < 8; nt++)
            #pragma unroll
            for (int k = 0; k < 4; k++) acc[mt][nt][k] = 0.0f;

    // rotating buffer byte-offsets (within XBUF region, relative to warp slot)
    uint32_t bufc = 0u;                      // consume: starts at buffer 0
    uint32_t buff = 4u * XBUF_B;             // fill:    starts at buffer 4

    const bool isH = (lid == 0) || (lid == 31);
    const uint32_t hbyte = (lid == 0) ? 12u : 272u;

    #pragma unroll 1
    for (int pp = 0; pp < 4; pp++) {
        #pragma unroll
        for (int sub = 0; sub < 2; sub++) {
            const int hp = 2 * pp + sub;

            // need group hp done; groups hp+1..hp+3 may stay in flight
            asm volatile("cp.async.wait_group 3;" ::: "memory");
            __syncwarp();

            // refill buffer `buff` for half-pass hp+4
            if (hp < 4) {
                const float* srcb = xb + (size_t)((hp + 4) * 8 + wid) * HW;
                const uint32_t dbase = wslot + buff;
                #pragma unroll
                for (int k = 0; k < 4; k++)
                    if (k < c_n)
                        asm volatile("cp.async.cg.shared.global [%0], [%1], 16, %2;"
                                     :: "r"(dbase + c_dst[k]), "l"(srcb + c_src[k]), "r"(c_ss[k]));
            }
            asm volatile("cp.async.commit_group;");
            buff += XBUF_B; if (buff >= (uint32_t)(NBUF * XBUF_B)) buff = 0u;

            // ---- stencil: warp wid converts channel hp*8+wid from buffer bufc ----
            const char* xc = smem + SM_XBUF + bufc + wid * XCH_B;
            bufc += XBUF_B; if (bufc >= (uint32_t)(NBUF * XBUF_B)) bufc = 0u;

            float2 u[6];
            float  uh[6];
            #pragma unroll
            for (int r = 0; r < 6; r++) {
                u[r]  = *(const float2*)(xc + r * XROW_B + 16 + 8 * lid);
                uh[r] = isH ? *(const float*)(xc + r * XROW_B + hbyte) : 0.0f;
            }

            float2 hs[6];
            #pragma unroll
            for (int r = 0; r < 6; r++) {
                const float av = axis_a(h0 - 1 + r);
                float lx = __shfl_up_sync(0xFFFFFFFFu, u[r].y, 1);
                float ry = __shfl_down_sync(0xFFFFFFFFu, u[r].x, 1);
                if (lid == 0)  lx = uh[r];
                if (lid == 31) ry = uh[r];
                float t  = fmaf(w2, u[r].y, w1 * u[r].x);
                float hx = fmaf(w0, lx, t);
                float hy = fmaf(w3, ry, t);
                hs[r] = make_float2(hx * av, hy * av);
            }

            const int c = hp * 8 + wid;
            #pragma unroll
            for (int r = 0; r < TILE_H; r++) {
                float sx = hs[r].x + hs[r + 1].x + hs[r + 2].x;
                float sy = hs[r].y + hs[r + 1].y + hs[r + 2].y;
                uint32_t off = (uint32_t)(c * RS_A + (r * 64 + 2 * lid) * 2);
                *(uint32_t*)(smem + SM_A + off) = pack_f16(sx, sy);
            }
        }

        // ---- publish A, MMA k-tile kt = pp ----
        __syncthreads();
        const int kt = pp;
        uint32_t af[2][4];
        #pragma unroll
        for (int mt = 0; mt < 2; mt++)
            ldsm_x4t(af[mt], sb + SM_A + a_off + (uint32_t)(kt * 16 * RS_A + mt * 32));
        #pragma unroll
        for (int h = 0; h < 2; h++) {
            uint32_t bf[2][4];
            #pragma unroll
            for (int pl = 0; pl < 2; pl++)
                ldsm_x4t(bf[pl], sb + SM_B + b_off + (uint32_t)(kt * 16 * RS_B + (2 * h + pl) * 32));
            #pragma unroll
            for (int mt = 0; mt < 2; mt++)
                #pragma unroll
                for (int ntl = 0; ntl < 4; ntl++)
                    mma_f16(acc[mt][h * 4 + ntl], af[mt],
                            bf[ntl >> 1][(ntl & 1) * 2], bf[ntl >> 1][(ntl & 1) * 2 + 1]);
        }
    }

    // ---- epilogue: dp-scale into smem D stage (overlays A+B+XBUF), coalesced STG ----
    __syncthreads();   // all ldsm/XBUF reads done before overwrite

    const int gh = h0 + (wid >> 1);
    const int colb = (wid & 1) * 32;
    const float ah_ = axis_a(gh);
    #pragma unroll
    for (int mt = 0; mt < 2; mt++) {
        #pragma unroll
        for (int half = 0; half < 2; half++) {
            int tx = mt * 16 + half * 8 + (lid >> 2);
            float dp = ah_ * axis_a(bx * TILE_W + colb + tx);
            int m = wid * 32 + tx;
            #pragma unroll
            for (int nt = 0; nt < 8; nt++) {
                int ch = nt * 8 + (lid & 3) * 2;
                smemf[(uint32_t)(ch * RS_DW + m)]       = acc[mt][nt][half * 2 + 0] * dp;
                smemf[(uint32_t)((ch + 1) * RS_DW + m)] = acc[mt][nt][half * 2 + 1] * dp;
            }
        }
    }
    __syncthreads();

    // readback: [ch][r (4)][64 cols], full-line STG.128
    float* ob = out + (size_t)b * COUT * HW + (size_t)h0 * WW + bx * TILE_W;
    #pragma unroll
    for (int i = 0; i < 16; i++) {
        int idx = tid + i * TB;
        int k  = idx & 15;
        int rr = (idx >> 4) & 3;
        int ch = idx >> 6;
        float4 val = *(float4*)(smemf + (uint32_t)(ch * RS_DW + rr * 64 + k * 4));
        *(float4*)(ob + (size_t)ch * HW + (size_t)rr * WW + k * 4) = val;
    }
}

extern "C" void kernel_launch(void* const* d_in, const int* in_sizes, int n_in,
                              void* d_out, int out_size)
{
    const float* x = (const float*)d_in[0];   // [4, 64, 512, 512]
    const float* w = (const float*)d_in[1];   // [1, 64, 64]
    float* out = (float*)d_out;

    cudaFuncSetAttribute(gcn_mma_kernel,
                         cudaFuncAttributeMaxDynamicSharedMemorySize, SM_TOTAL);

    dim3 grid(WW / TILE_W, HH / TILE_H, 4);
    gcn_mma_kernel<<<grid, TB, SM_TOTAL>>>(x, w, out);
}

// round 17
// speedup vs baseline: 1.5248x; 1.5248x over previous
#include <cuda_runtime.h>
#include <cuda_fp16.h>
#include <cstdint>

#define TB      256
#define TILE_H  4
#define TILE_W  64
#define CIN     64
#define COUT    64
#define HH      512
#define WW      512
#define HW      (HH * WW)

// smem layout (bytes)
#define RS_A    528
#define RS_B    144
#define RS_DW   264                           // words; ≡8 mod 32
#define SM_A    0
#define SM_B    (SM_A + CIN * RS_A)          // 33792
#define SM_XBUF (SM_B + CIN * RS_B)          // 43008
// XBUF: 4 buffers x [8 warp-slots][6 rows][18 float4]  (cols bx*64-4 .. bx*64+67)
#define XROW_B  288
#define XCH_B   1728
#define XBUF_B  13824
#define SM_TOTAL (SM_XBUF + 4 * XBUF_B)      // 98304  (2 CTAs/SM)
// D stage overlays A+B+XBUF[0..]: 64*264*4 = 67584 <= 98304 OK

#define NCHUNK_W 108                          // 6 rows * 18 chunks per warp-halfpass

__device__ __forceinline__ float axis_a(int i) {
    return (i == 0 || i == HH - 1) ? 0.70710678118654752f : 0.57735026918962576f;
}

__device__ __forceinline__ uint32_t pack_f16(float lo, float hi) {
    uint32_t r;
    asm("cvt.rn.f16x2.f32 %0, %1, %2;" : "=r"(r) : "f"(hi), "f"(lo));
    return r;
}

__device__ __forceinline__ void ldsm_x4t(uint32_t* r, uint32_t addr) {
    asm volatile("ldmatrix.sync.aligned.m8n8.x4.trans.shared.b16 {%0,%1,%2,%3}, [%4];"
                 : "=r"(r[0]), "=r"(r[1]), "=r"(r[2]), "=r"(r[3]) : "r"(addr));
}
__device__ __forceinline__ void mma_f16(float* d, const uint32_t* a, uint32_t b0, uint32_t b1) {
    asm volatile(
        "mma.sync.aligned.m16n8k16.row.col.f32.f16.f16.f32 "
        "{%0,%1,%2,%3}, {%4,%5,%6,%7}, {%8,%9}, {%0,%1,%2,%3};"
        : "+f"(d[0]), "+f"(d[1]), "+f"(d[2]), "+f"(d[3])
        : "r"(a[0]), "r"(a[1]), "r"(a[2]), "r"(a[3]), "r"(b0), "r"(b1));
}

__global__ void __launch_bounds__(TB, 2) gcn_mma_kernel(
    const float* __restrict__ x,     // [B, 64, 512, 512]
    const float* __restrict__ wmat,  // [64, 64] (c, o)
    float* __restrict__ out)         // [B, 64, 512, 512]
{
    extern __shared__ __align__(128) char smem[];
    const uint32_t sb = (uint32_t)__cvta_generic_to_shared(smem);
    float* smemf = (float*)smem;
    const int tid = threadIdx.x;
    const int wid = tid >> 5;
    const int lid = tid & 31;
    const int bx = blockIdx.x, by = blockIdx.y, b = blockIdx.z;

    const int h0 = by * TILE_H;
    const float* xb = x + (size_t)b * CIN * HW;

    // ---- precompute this lane's copy chunks (<=4), once ----
    uint32_t c_dst[4];
    int      c_src[4];
    int      c_ss[4];
    int      c_n = 0;
    #pragma unroll
    for (int k = 0; k < 4; k++) {
        int id = lid + 32 * k;
        if (id < NCHUNK_W) {
            int row = id / 18;
            int j   = id - row * 18;
            int gh  = h0 - 1 + row;
            int g   = bx * TILE_W - 4 + 4 * j;
            bool ok = ((unsigned)gh < HH) && (g >= 0) && (g + 3 < WW);
            c_dst[c_n] = (uint32_t)(row * XROW_B + j * 16);
            c_src[c_n] = ok ? (gh * WW + g) : 0;
            c_ss[c_n]  = ok ? 16 : 0;
            c_n++;
        }
    }
    const uint32_t wslot = sb + SM_XBUF + (uint32_t)(wid * XCH_B);

    // prologue: stream half-passes 0..2 into buffers 0..2 (prefetch depth 3)
    #pragma unroll
    for (int hp = 0; hp < 3; hp++) {
        const float* srcb = xb + (size_t)(hp * 8 + wid) * HW;
        const uint32_t dbase = wslot + (uint32_t)(hp * XBUF_B);
        #pragma unroll
        for (int k = 0; k < 4; k++)
            if (k < c_n)
                asm volatile("cp.async.cg.shared.global [%0], [%1], 16, %2;"
                             :: "r"(dbase + c_dst[k]), "l"(srcb + c_src[k]), "r"(c_ss[k]));
        asm volatile("cp.async.commit_group;");
    }

    // ---- B tile: W[c][o] -> smem [c][o] fp16, coalesced 32-bit STS ----
    {
        const float2* w2 = (const float2*)wmat;
        #pragma unroll
        for (int it = tid; it < CIN * COUT / 2; it += TB) {
            int c  = it >> 5;
            int o2 = it & 31;
            float2 v = w2[it];
            *(uint32_t*)(smem + SM_B + (uint32_t)(c * RS_B + o2 * 4)) = pack_f16(v.x, v.y);
        }
    }

    // per-lane stencil constants (lane owns 2 cols: cbase, cbase+1)
    const int cbase = bx * TILE_W + 2 * lid;
    const bool lok = (cbase - 1 >= 0);
    const bool rok = (cbase + 2 <= WW - 1);
    const float w0 = lok ? axis_a(cbase - 1) : 0.0f;
    const float w1 = axis_a(cbase);
    const float w2 = axis_a(cbase + 1);
    const float w3 = rok ? axis_a(cbase + 2) : 0.0f;

    // MMA fragment addresses
    const uint32_t a_off = (uint32_t)((lid & 7) + ((lid >> 4) & 1) * 8) * RS_A
                         + (uint32_t)(wid * 32 + ((lid >> 3) & 1) * 8) * 2;
    const uint32_t b_off = (uint32_t)((lid & 7) + ((lid >> 3) & 1) * 8) * RS_B
                         + (uint32_t)(((lid >> 4) & 1) * 8) * 2;

    float acc[2][8][4];
    #pragma unroll
    for (int mt = 0; mt < 2; mt++)
        #pragma unroll
        for (int nt = 0; nt < 8; nt++)
            #pragma unroll
            for (int k = 0; k < 4; k++) acc[mt][nt][k] = 0.0f;

    #pragma unroll 1
    for (int hp = 0; hp < 8; hp++) {
        // committed so far = 3 + hp; need group hp done -> allow 2 outstanding
        asm volatile("cp.async.wait_group 2;" ::: "memory");
        __syncwarp();

        // refill buffer (hp+3)&3 for half-pass hp+3 (max in-flight time)
        if (hp < 5) {
            const float* srcb = xb + (size_t)((hp + 3) * 8 + wid) * HW;
            const uint32_t dbase = wslot + (uint32_t)(((hp + 3) & 3) * XBUF_B);
            #pragma unroll
            for (int k = 0; k < 4; k++)
                if (k < c_n)
                    asm volatile("cp.async.cg.shared.global [%0], [%1], 16, %2;"
                                 :: "r"(dbase + c_dst[k]), "l"(srcb + c_src[k]), "r"(c_ss[k]));
        }
        asm volatile("cp.async.commit_group;");

        // ---- stencil: warp wid converts channel hp*8+wid from buffer hp&3 ----
        const char* xc = smem + SM_XBUF + (hp & 3) * XBUF_B + wid * XCH_B;
        float2 u[6];
        float  uh[6];
        const bool isH = (lid == 0) || (lid == 31);
        const uint32_t hbyte = (lid == 0) ? 12u : 272u;
        #pragma unroll
        for (int r = 0; r < 6; r++) {
            u[r]  = *(const float2*)(xc + r * XROW_B + 16 + 8 * lid);
            uh[r] = isH ? *(const float*)(xc + r * XROW_B + hbyte) : 0.0f;
        }

        float2 hs[6];
        #pragma unroll
        for (int r = 0; r < 6; r++) {
            const float av = axis_a(h0 - 1 + r);
            float lx = __shfl_up_sync(0xFFFFFFFFu, u[r].y, 1);
            float ry = __shfl_down_sync(0xFFFFFFFFu, u[r].x, 1);
            if (lid == 0)  lx = uh[r];
            if (lid == 31) ry = uh[r];
            float t  = fmaf(w2, u[r].y, w1 * u[r].x);
            float hx = fmaf(w0, lx, t);
            float hy = fmaf(w3, ry, t);
            hs[r] = make_float2(hx * av, hy * av);
        }

        // vertical 3-sum, fp16 pack, STS into A channel hp*8+wid
        {
            const int c = hp * 8 + wid;
            #pragma unroll
            for (int r = 0; r < TILE_H; r++) {
                float sx = hs[r].x + hs[r + 1].x + hs[r + 2].x;
                float sy = hs[r].y + hs[r + 1].y + hs[r + 2].y;
                uint32_t off = (uint32_t)(c * RS_A + (r * 64 + 2 * lid) * 2);
                *(uint32_t*)(smem + SM_A + off) = pack_f16(sx, sy);
            }
        }

        // ---- after odd half-pass: publish A, MMA k-tile kt = hp>>1 ----
        if (hp & 1) {
            __syncthreads();
            const int kt = hp >> 1;
            uint32_t af[2][4];
            #pragma unroll
            for (int mt = 0; mt < 2; mt++)
                ldsm_x4t(af[mt], sb + SM_A + a_off + (uint32_t)(kt * 16 * RS_A + mt * 32));
            #pragma unroll
            for (int h = 0; h < 2; h++) {
                uint32_t bf[2][4];
                #pragma unroll
                for (int pl = 0; pl < 2; pl++)
                    ldsm_x4t(bf[pl], sb + SM_B + b_off + (uint32_t)(kt * 16 * RS_B + (2 * h + pl) * 32));
                #pragma unroll
                for (int mt = 0; mt < 2; mt++)
                    #pragma unroll
                    for (int ntl = 0; ntl < 4; ntl++)
                        mma_f16(acc[mt][h * 4 + ntl], af[mt],
                                bf[ntl >> 1][(ntl & 1) * 2], bf[ntl >> 1][(ntl & 1) * 2 + 1]);
            }
        }
    }

    // ---- epilogue: dp-scale into smem D stage (overlays A+B+XBUF), coalesced STG ----
    __syncthreads();   // all ldsm/XBUF reads done before overwrite

    const int gh = h0 + (wid >> 1);
    const int colb = (wid & 1) * 32;
    const float ah_ = axis_a(gh);
    #pragma unroll
    for (int mt = 0; mt < 2; mt++) {
        #pragma unroll
        for (int half = 0; half < 2; half++) {
            int tx = mt * 16 + half * 8 + (lid >> 2);
            float dp = ah_ * axis_a(bx * TILE_W + colb + tx);
            int m = wid * 32 + tx;
            #pragma unroll
            for (int nt = 0; nt < 8; nt++) {
                int ch = nt * 8 + (lid & 3) * 2;
                smemf[(uint32_t)(ch * RS_DW + m)]       = acc[mt][nt][half * 2 + 0] * dp;
                smemf[(uint32_t)((ch + 1) * RS_DW + m)] = acc[mt][nt][half * 2 + 1] * dp;
            }
        }
    }
    __syncthreads();

    // readback: [ch][r (4)][64 cols], full-line STG.128
    float* ob = out + (size_t)b * COUT * HW + (size_t)h0 * WW + bx * TILE_W;
    #pragma unroll
    for (int i = 0; i < 16; i++) {
        int idx = tid + i * TB;
        int k  = idx & 15;
        int rr = (idx >> 4) & 3;
        int ch = idx >> 6;
        float4 val = *(float4*)(smemf + (uint32_t)(ch * RS_DW + rr * 64 + k * 4));
        *(float4*)(ob + (size_t)ch * HW + (size_t)rr * WW + k * 4) = val;
    }
}

extern "C" void kernel_launch(void* const* d_in, const int* in_sizes, int n_in,
                              void* d_out, int out_size)
{
    const float* x = (const float*)d_in[0];   // [4, 64, 512, 512]
    const float* w = (const float*)d_in[1];   // [1, 64, 64]
    float* out = (float*)d_out;

    cudaFuncSetAttribute(gcn_mma_kernel,
                         cudaFuncAttributeMaxDynamicSharedMemorySize, SM_TOTAL);

    dim3 grid(WW / TILE_W, HH / TILE_H, 4);
    gcn_mma_kernel<<<grid, TB, SM_TOTAL>>>(x, w, out);
}